// round 10
// baseline (speedup 1.0000x reference)
#include <cuda_runtime.h>
#include <cuda_fp16.h>
#include <cstdint>

// Problem constants
#define B_ROWS   65536
#define C_COLS   300
#define A_DIM    32
#define XSTRIDE  600

#define THREADS  256
#define NWARPS   8
#define GROUP    32
#define NGROUPS  (B_ROWS / GROUP)        // 2048
#define GRID     1024                    // exactly 2 groups per CTA

#define IDXCAP   40

#define CS       312                     // cards f32 stride: LDS.64 conflict-free
#define APS      36

#define CARDS_WORDS (GROUP * CS)         // 9984
#define AP_WORDS    (GROUP * APS)        // 1152
#define PW_WORDS    96
#define SMEM_WORDS  (CARDS_WORDS + AP_WORDS + NWARPS * PW_WORDS)  // 11904
#define SMEM_BYTES  (SMEM_WORDS * 4)     // 47616 -> 4 CTAs/SM

// W in two packed-fp16 global layouts (L1-resident, shared across CTAs on an SM).
// Every CTA writes identical values (benign race), reads only after its own writes.
__device__ uint32_t g_Wp[152 * 32];      // [kp][a]  half2{W[2kp][a],W[2kp+1][a]}, kp>=150 zero
__device__ uint32_t g_Wh2[300 * 16];     // [c][ap]  half2{W[c][2ap],W[c][2ap+1]}

__device__ __forceinline__ uint32_t pack_f16x2(float lo, float hi) {
    uint32_t r;                          // first src -> hi half, second -> lo half
    asm("cvt.rn.f16x2.f32 %0, %1, %2;" : "=r"(r) : "f"(hi), "f"(lo));
    return r;
}
__device__ __forceinline__ void mma_f16_k16(float& d0, float& d1, float& d2, float& d3,
                                            uint32_t a0, uint32_t a1, uint32_t a2, uint32_t a3,
                                            uint32_t b0, uint32_t b1) {
    asm("mma.sync.aligned.m16n8k16.row.col.f32.f16.f16.f32 "
        "{%0,%1,%2,%3},{%4,%5,%6,%7},{%8,%9},{%0,%1,%2,%3};"
        : "+f"(d0), "+f"(d1), "+f"(d2), "+f"(d3)
        : "r"(a0), "r"(a1), "r"(a2), "r"(a3), "r"(b0), "r"(b1));
}
__device__ __forceinline__ void cp16(uint32_t saddr, const float* gaddr) {
    asm volatile("cp.async.cg.shared.global [%0], [%1], 16;" :: "r"(saddr), "l"(gaddr));
}
__device__ __forceinline__ void cp_commit() { asm volatile("cp.async.commit_group;"); }
__device__ __forceinline__ void cp_wait0()  { asm volatile("cp.async.wait_group 0;"); }

__global__ __launch_bounds__(THREADS, 4)
void draftbot_kernel(const float* __restrict__ X,
                     const float* __restrict__ W,
                     float* __restrict__ Out)
{
    extern __shared__ float smem[];
    float* cards = smem;                             // [32][312] f32
    float* apbuf = smem + CARDS_WORDS;               // [32][36]
    const int tid  = threadIdx.x;
    const int lane = tid & 31;
    const int warp = tid >> 5;
    float* pw   = apbuf + AP_WORDS + warp * PW_WORDS;
    int*   widx = (int*)pw;                          // [40]
    float* scw  = pw + IDXCAP;                       // [40]

    const uint32_t cards_u32 = (uint32_t)__cvta_generic_to_shared(cards);

    auto stage = [&](int g) {
        const float* gb = X + (size_t)g * GROUP * XSTRIDE + C_COLS;
        #pragma unroll 1
        for (int t = 0; t < 10; t++) {
            int idx = tid + THREADS * t;             // valid < 2400
            if (idx < GROUP * 75) {
                int row = idx / 75, ch = idx - row * 75;
                cp16(cards_u32 + (uint32_t)(row * CS + ch * 4) * 4,
                     gb + (size_t)row * XSTRIDE + ch * 4);
            }
        }
        cp_commit();
    };

    int g = blockIdx.x;
    stage(g);                                        // prologue stage (overlaps W packing)

    // zero-pad cards words 300..303 per row (K tail for kp=150,151); never overwritten
    if (tid < GROUP) *(float4*)(cards + tid * CS + 300) = make_float4(0.f, 0.f, 0.f, 0.f);

    // pack W into the two global fp16 layouts (redundant per CTA, identical values)
    for (int i = tid; i < 152 * 32; i += THREADS) {
        int kp = i >> 5, a = i & 31;
        float lo = (2 * kp     < C_COLS) ? W[(2 * kp)     * A_DIM + a] : 0.0f;
        float hi = (2 * kp + 1 < C_COLS) ? W[(2 * kp + 1) * A_DIM + a] : 0.0f;
        g_Wp[i] = pack_f16x2(lo, hi);
    }
    for (int i = tid; i < 300 * 16; i += THREADS) {
        int c = i >> 4, ap2 = i & 15;
        g_Wh2[i] = pack_f16x2(W[c * A_DIM + 2 * ap2], W[c * A_DIM + 2 * ap2 + 1]);
    }

    const unsigned FULL = 0xffffffffu;
    const int rt = warp & 1;                         // phase-1 row tile (16 rows)
    const int nt = warp >> 1;                        // phase-1 n tile (8 cols)
    const int gq = lane >> 2, tq = lane & 3;         // mma fragment coords
    const int qid = lane >> 3;                       // phase-2 octets
    const int sub = lane & 7;

    for (; g < NGROUPS; g += GRID) {
        cp_wait0();
        __syncthreads();                             // cards ready; apbuf free

        // ---------- phase 1: ap = cards @ W + 1 (fp16 mma, convert-on-load) ----------
        {
            float d0 = 0.f, d1 = 0.f, d2 = 0.f, d3 = 0.f;
            const float* A0 = cards + (rt * 16 + gq) * CS;
            const float* A1 = A0 + 8 * CS;
            const uint32_t* Bp = g_Wp + nt * 8 + gq;
            #pragma unroll
            for (int kk = 0; kk < 19; kk++) {
                const int kp0 = kk * 8;
                float2 f0 = *(const float2*)(A0 + 2 * (kp0 + tq));
                float2 f1 = *(const float2*)(A1 + 2 * (kp0 + tq));
                float2 f2 = *(const float2*)(A0 + 2 * (kp0 + tq + 4));
                float2 f3 = *(const float2*)(A1 + 2 * (kp0 + tq + 4));
                uint32_t a0 = pack_f16x2(f0.x, f0.y);
                uint32_t a1 = pack_f16x2(f1.x, f1.y);
                uint32_t a2 = pack_f16x2(f2.x, f2.y);
                uint32_t a3 = pack_f16x2(f3.x, f3.y);
                uint32_t b0 = Bp[(kp0 + tq) * 32];
                uint32_t b1 = Bp[(kp0 + tq + 4) * 32];
                mma_f16_k16(d0, d1, d2, d3, a0, a1, a2, a3, b0, b1);
            }
            float* ap0 = apbuf + (rt * 16 + gq) * APS + nt * 8 + 2 * tq;
            *(float2*)ap0             = make_float2(d0 + 1.f, d1 + 1.f);
            *(float2*)(ap0 + 8 * APS) = make_float2(d2 + 1.f, d3 + 1.f);
        }
        __syncthreads();                             // ap ready; cards free

        if (g + GRID < NGROUPS) stage(g + GRID);     // prefetch overlaps phase 2

        // ---------- phase 2: 4 rows/warp ----------
        #pragma unroll 1
        for (int i = 0; i < 4; i++) {
            const int lrow = warp * 4 + i;
            const int grow = g * GROUP + lrow;

            // scan-based compaction (order-free) of nonzero option columns
            const float4* osrc = (const float4*)(X + (size_t)grow * XSTRIDE);
            float4 ovv[3];
            ovv[0] = osrc[lane];
            ovv[1] = (lane + 32 < 75) ? osrc[lane + 32] : make_float4(0,0,0,0);
            ovv[2] = (lane + 64 < 75) ? osrc[lane + 64] : make_float4(0,0,0,0);
            unsigned lm = 0;
            #pragma unroll
            for (int t = 0; t < 3; t++) {
                lm |= (ovv[t].x != 0.f ? 1u : 0u) << (4 * t + 0);
                lm |= (ovv[t].y != 0.f ? 1u : 0u) << (4 * t + 1);
                lm |= (ovv[t].z != 0.f ? 1u : 0u) << (4 * t + 2);
                lm |= (ovv[t].w != 0.f ? 1u : 0u) << (4 * t + 3);
            }
            int lc = __popc(lm);
            int incl = lc;
            #pragma unroll
            for (int o = 1; o < 32; o <<= 1) {
                int n = __shfl_up_sync(FULL, incl, o);
                if (lane >= o) incl += n;
            }
            int cn = __shfl_sync(FULL, incl, 31);
            int pos = incl - lc;
            unsigned mm = lm;
            while (mm) {
                int b = __ffs(mm) - 1; mm &= mm - 1;
                if (pos < IDXCAP) widx[pos] = 4 * (lane + 32 * (b >> 2)) + (b & 3);
                pos++;
            }
            if (cn > IDXCAP) cn = IDXCAP;
            __syncwarp();

            // scores: 8 lanes/column, 4 columns in flight, fp16 W gather
            float4 av = *(const float4*)(apbuf + lrow * APS + sub * 4);
            const int nch = (cn + 3) >> 2;
            #pragma unroll 2
            for (int ch = 0; ch < nch; ch++) {
                int  j   = ch * 4 + qid;
                bool val = j < cn;
                int  c   = val ? widx[j] : 0;
                uint2 hw = *(const uint2*)(g_Wh2 + c * 16 + sub * 2);
                float2 w0 = __half22float2(*reinterpret_cast<const __half2*>(&hw.x));
                float2 w1 = __half22float2(*reinterpret_cast<const __half2*>(&hw.y));
                float p = av.x * w0.x + av.y * w0.y + av.z * w1.x + av.w * w1.y;
                p += __shfl_xor_sync(FULL, p, 1);
                p += __shfl_xor_sync(FULL, p, 2);
                p += __shfl_xor_sync(FULL, p, 4);
                if (val && sub == 0) scw[j] = p;
            }
            __syncwarp();

            // masked log-softmax (zeros always present in the row)
            int  j0 = lane, j1 = lane + 32;
            bool v0 = j0 < cn, v1 = j1 < cn;
            float s0 = v0 ? scw[j0] : 0.0f;
            float s1 = v1 ? scw[j1] : 0.0f;
            int   c0 = v0 ? widx[j0] : -1;
            int   c1 = v1 ? widx[j1] : -1;

            float m = fmaxf(fmaxf(s0, s1), 0.0f);
            #pragma unroll
            for (int o = 16; o > 0; o >>= 1) m = fmaxf(m, __shfl_xor_sync(FULL, m, o));

            float g0 = (s0 > 0.f) ? 1.f : ((s0 < 0.f) ? -1.f : 0.f);
            float g1 = (s1 > 0.f) ? 1.f : ((s1 < 0.f) ? -1.f : 0.f);
            float sum = g0 * __expf(s0 - m * g0) + g1 * __expf(s1 - m * g1);
            #pragma unroll
            for (int o = 16; o > 0; o >>= 1) sum += __shfl_xor_sync(FULL, sum, o);
            float lse = __logf(sum);

            float* orow = Out + (size_t)grow * C_COLS;
            #pragma unroll
            for (int t = 0; t < 3; t++) {
                int gi = lane + 32 * t;
                if (gi < 75) *(float4*)(orow + 4 * gi) = make_float4(0.f, 0.f, 0.f, 0.f);
            }
            __syncwarp();
            if (c0 >= 0) orow[c0] = g0 * ((s0 - m * g0) - lse);
            if (c1 >= 0) orow[c1] = g1 * ((s1 - m * g1) - lse);
            __syncwarp();
        }
    }
}

extern "C" void kernel_launch(void* const* d_in, const int* in_sizes, int n_in,
                              void* d_out, int out_size)
{
    const float* X = (const float*)d_in[0];
    const float* W = (const float*)d_in[1];
    if (n_in >= 2 && in_sizes[0] < in_sizes[1]) {   // defensively order by size
        const float* t = X; X = W; W = t;
    }
    float* Out = (float*)d_out;

    cudaFuncSetAttribute(draftbot_kernel,
                         cudaFuncAttributeMaxDynamicSharedMemorySize, SMEM_BYTES);
    draftbot_kernel<<<GRID, THREADS, SMEM_BYTES>>>(X, W, Out);
}

// round 11
// speedup vs baseline: 1.0649x; 1.0649x over previous
#include <cuda_runtime.h>
#include <cstdint>

// Problem constants
#define B_ROWS   65536
#define C_COLS   300
#define A_DIM    32
#define XSTRIDE  600

#define THREADS  256
#define NWARPS   8
#define GROUP    32
#define NGROUPS  (B_ROWS / GROUP)        // 2048
#define GRID     NGROUPS                 // one group per CTA; HW load-balances

#define IDXCAP   40

// packed half2 layouts (uint32 words)
#define WPS      40                      // Wp stride: banks 8tq+gq distinct
#define CPS      156                     // cardsp stride: banks 28gq+tq distinct
#define APS      36                      // apbuf stride (floats)

#define WP_WORDS    (152 * WPS)          // 6080 (kp 0..151; k>=300 zero-padded)
#define CP_WORDS    (GROUP * CPS)        // 4992
#define AP_WORDS    (GROUP * APS)        // 1152
#define PW_WORDS    96
#define SMEM_WORDS  (WP_WORDS + CP_WORDS + AP_WORDS + NWARPS * PW_WORDS)  // 12992
#define SMEM_BYTES  (SMEM_WORDS * 4)     // 51968 -> 4 CTAs/SM

__device__ __forceinline__ uint32_t pack_f16x2(float lo, float hi) {
    uint32_t r;                          // first src -> hi half, second -> lo half
    asm("cvt.rn.f16x2.f32 %0, %1, %2;" : "=r"(r) : "f"(hi), "f"(lo));
    return r;
}
__device__ __forceinline__ void mma_f16_k16(float& d0, float& d1, float& d2, float& d3,
                                            uint32_t a0, uint32_t a1, uint32_t a2, uint32_t a3,
                                            uint32_t b0, uint32_t b1) {
    asm("mma.sync.aligned.m16n8k16.row.col.f32.f16.f16.f32 "
        "{%0,%1,%2,%3},{%4,%5,%6,%7},{%8,%9},{%0,%1,%2,%3};"
        : "+f"(d0), "+f"(d1), "+f"(d2), "+f"(d3)
        : "r"(a0), "r"(a1), "r"(a2), "r"(a3), "r"(b0), "r"(b1));
}

__global__ __launch_bounds__(THREADS, 4)
void draftbot_kernel(const float* __restrict__ X,
                     const float* __restrict__ W,
                     float* __restrict__ Out)
{
    extern __shared__ uint32_t smw[];
    uint32_t* Wp     = smw;                          // [152][40] half2 (k-pairs x a)
    uint32_t* cardsp = smw + WP_WORDS;               // [32][156] half2 (row x k-pairs)
    float*    apbuf  = (float*)(smw + WP_WORDS + CP_WORDS);  // [32][36]
    const int tid  = threadIdx.x;
    const int lane = tid & 31;
    const int warp = tid >> 5;
    float* pw   = apbuf + AP_WORDS + warp * PW_WORDS;
    int*   widx = (int*)pw;                          // [40]
    float* scw  = pw + IDXCAP;                       // [40]

    const int g = blockIdx.x;                        // this CTA's group

    // ---- stage cards of group g (f32 -> f16x2), overlapped with W packing ----
    {
        const float* gb = X + (size_t)g * GROUP * XSTRIDE + C_COLS;
        #pragma unroll 1
        for (int t = 0; t < 10; t++) {
            int idx = tid + THREADS * t;             // valid < 2400
            if (idx < GROUP * 75) {
                int row = idx / 75, ch = idx - row * 75;
                float4 v = *(const float4*)(gb + (size_t)row * XSTRIDE + 4 * ch);
                uint2 h;
                h.x = pack_f16x2(v.x, v.y);
                h.y = pack_f16x2(v.z, v.w);
                *(uint2*)(cardsp + row * CPS + 2 * ch) = h;
            }
        }
        if (tid < GROUP * 2) {                       // cardsp kp 150,151 = 0
            int r = tid >> 1, kp = 150 + (tid & 1);
            cardsp[r * CPS + kp] = 0u;
        }
    }

    // ---- pack W into smem fp16 layout (zero-padded to kp<152) ----
    for (int i = tid; i < 152 * 32; i += THREADS) {
        int kp = i >> 5, a = i & 31;
        float lo = (2 * kp     < C_COLS) ? W[(2 * kp)     * A_DIM + a] : 0.0f;
        float hi = (2 * kp + 1 < C_COLS) ? W[(2 * kp + 1) * A_DIM + a] : 0.0f;
        Wp[kp * WPS + a] = pack_f16x2(lo, hi);
    }
    __syncthreads();                                 // cards + W ready

    const unsigned FULL = 0xffffffffu;
    const int rt = warp & 1;                         // phase-1 row tile (16 rows)
    const int nt = warp >> 1;                        // phase-1 n tile (8 cols)
    const int gq = lane >> 2, tq = lane & 3;         // mma fragment coords
    const int qid = lane >> 3;                       // phase-2 octets
    const int sub = lane & 7;

    // ---------- phase 1: ap = cards @ W + 1  (fp16 m16n8k16) ----------
    {
        float d0 = 0.f, d1 = 0.f, d2 = 0.f, d3 = 0.f;
        const uint32_t* A0 = cardsp + (rt * 16 + gq) * CPS;
        const uint32_t* A1 = A0 + 8 * CPS;
        const uint32_t* Bp = Wp + nt * 8 + gq;
        #pragma unroll
        for (int kk = 0; kk < 19; kk++) {            // 19 * k16 = 304 (padded)
            const int kp0 = kk * 8;
            uint32_t a0 = A0[kp0 + tq];
            uint32_t a1 = A1[kp0 + tq];
            uint32_t a2 = A0[kp0 + tq + 4];
            uint32_t a3 = A1[kp0 + tq + 4];
            uint32_t b0 = Bp[(kp0 + tq) * WPS];
            uint32_t b1 = Bp[(kp0 + tq + 4) * WPS];
            mma_f16_k16(d0, d1, d2, d3, a0, a1, a2, a3, b0, b1);
        }
        float* ap0 = apbuf + (rt * 16 + gq) * APS + nt * 8 + 2 * tq;
        *(float2*)ap0             = make_float2(d0 + 1.f, d1 + 1.f);
        *(float2*)(ap0 + 8 * APS) = make_float2(d2 + 1.f, d3 + 1.f);
    }
    __syncthreads();                                 // ap ready

    // ---------- phase 2: 4 rows/warp, sparse scores + masked log-softmax ----------
    #pragma unroll 1
    for (int i = 0; i < 4; i++) {
        const int lrow = warp * 4 + i;
        const int grow = g * GROUP + lrow;

        // scan-based compaction (order-free) of nonzero option columns
        const float4* osrc = (const float4*)(X + (size_t)grow * XSTRIDE);
        float4 ovv[3];
        ovv[0] = osrc[lane];
        ovv[1] = (lane + 32 < 75) ? osrc[lane + 32] : make_float4(0,0,0,0);
        ovv[2] = (lane + 64 < 75) ? osrc[lane + 64] : make_float4(0,0,0,0);
        unsigned lm = 0;
        #pragma unroll
        for (int t = 0; t < 3; t++) {
            lm |= (ovv[t].x != 0.f ? 1u : 0u) << (4 * t + 0);
            lm |= (ovv[t].y != 0.f ? 1u : 0u) << (4 * t + 1);
            lm |= (ovv[t].z != 0.f ? 1u : 0u) << (4 * t + 2);
            lm |= (ovv[t].w != 0.f ? 1u : 0u) << (4 * t + 3);
        }
        int lc = __popc(lm);
        int incl = lc;
        #pragma unroll
        for (int o = 1; o < 32; o <<= 1) {
            int n = __shfl_up_sync(FULL, incl, o);
            if (lane >= o) incl += n;
        }
        int cn = __shfl_sync(FULL, incl, 31);
        int pos = incl - lc;
        unsigned mm = lm;
        while (mm) {
            int b = __ffs(mm) - 1; mm &= mm - 1;
            if (pos < IDXCAP) widx[pos] = 4 * (lane + 32 * (b >> 2)) + (b & 3);
            pos++;
        }
        if (cn > IDXCAP) cn = IDXCAP;
        __syncwarp();

        // scores: 8 lanes per column, 4 columns in flight (fp32 W from global, L1-hot)
        float4 av = *(const float4*)(apbuf + lrow * APS + sub * 4);
        const int nch = (cn + 3) >> 2;
        #pragma unroll 2
        for (int ch = 0; ch < nch; ch++) {
            int  j   = ch * 4 + qid;
            bool val = j < cn;
            int  c   = val ? widx[j] : 0;
            float4 wv = *(const float4*)(W + c * A_DIM + sub * 4);
            float p = av.x * wv.x + av.y * wv.y + av.z * wv.z + av.w * wv.w;
            p += __shfl_xor_sync(FULL, p, 1);
            p += __shfl_xor_sync(FULL, p, 2);
            p += __shfl_xor_sync(FULL, p, 4);
            if (val && sub == 0) scw[j] = p;
        }
        __syncwarp();

        // masked log-softmax (zeros always present in the row)
        int  j0 = lane, j1 = lane + 32;
        bool v0 = j0 < cn, v1 = j1 < cn;
        float s0 = v0 ? scw[j0] : 0.0f;
        float s1 = v1 ? scw[j1] : 0.0f;
        int   c0 = v0 ? widx[j0] : -1;
        int   c1 = v1 ? widx[j1] : -1;

        float m = fmaxf(fmaxf(s0, s1), 0.0f);
        #pragma unroll
        for (int o = 16; o > 0; o >>= 1) m = fmaxf(m, __shfl_xor_sync(FULL, m, o));

        float g0 = (s0 > 0.f) ? 1.f : ((s0 < 0.f) ? -1.f : 0.f);
        float g1 = (s1 > 0.f) ? 1.f : ((s1 < 0.f) ? -1.f : 0.f);
        float sum = g0 * __expf(s0 - m * g0) + g1 * __expf(s1 - m * g1);
        #pragma unroll
        for (int o = 16; o > 0; o >>= 1) sum += __shfl_xor_sync(FULL, sum, o);
        float lse = __logf(sum);

        float* orow = Out + (size_t)grow * C_COLS;
        #pragma unroll
        for (int t = 0; t < 3; t++) {
            int gi = lane + 32 * t;
            if (gi < 75) *(float4*)(orow + 4 * gi) = make_float4(0.f, 0.f, 0.f, 0.f);
        }
        __syncwarp();
        if (c0 >= 0) orow[c0] = g0 * ((s0 - m * g0) - lse);
        if (c1 >= 0) orow[c1] = g1 * ((s1 - m * g1) - lse);
        __syncwarp();
    }
}

extern "C" void kernel_launch(void* const* d_in, const int* in_sizes, int n_in,
                              void* d_out, int out_size)
{
    const float* X = (const float*)d_in[0];
    const float* W = (const float*)d_in[1];
    if (n_in >= 2 && in_sizes[0] < in_sizes[1]) {   // defensively order by size
        const float* t = X; X = W; W = t;
    }
    float* Out = (float*)d_out;

    cudaFuncSetAttribute(draftbot_kernel,
                         cudaFuncAttributeMaxDynamicSharedMemorySize, SMEM_BYTES);
    draftbot_kernel<<<GRID, THREADS, SMEM_BYTES>>>(X, W, Out);
}

// round 12
// speedup vs baseline: 1.3611x; 1.2782x over previous
#include <cuda_runtime.h>
#include <cstdint>

// Problem constants
#define B_ROWS   65536
#define C_COLS   300
#define A_DIM    32
#define XSTRIDE  600

#define THREADS  256
#define NWARPS   8
#define GROUP    32
#define NGROUPS  (B_ROWS / GROUP)        // 2048
#define GRID     NGROUPS                 // one group per CTA

#define IDXCAP   40

#define CPS      156                     // cardsp stride (half2 words): conflict-free
#define APS      36                      // apbuf stride (floats)

#define CP_WORDS    (GROUP * CPS)        // 4992
#define AP_WORDS    (GROUP * APS)        // 1152
#define PW_WORDS    96
#define SMEM_WORDS  (CP_WORDS + AP_WORDS + NWARPS * PW_WORDS)  // 6912
#define SMEM_BYTES  (SMEM_WORDS * 4)     // 27648 B

// fp16-packed W, written once by pack_w_kernel: [kp][a] = half2{W[2kp][a], W[2kp+1][a]}
__device__ uint32_t g_Wp[152 * 32];      // kp >= 150 zero-padded

__device__ __forceinline__ uint32_t pack_f16x2(float lo, float hi) {
    uint32_t r;                          // first src -> hi half, second -> lo half
    asm("cvt.rn.f16x2.f32 %0, %1, %2;" : "=r"(r) : "f"(hi), "f"(lo));
    return r;
}
__device__ __forceinline__ void mma_f16_k16(float& d0, float& d1, float& d2, float& d3,
                                            uint32_t a0, uint32_t a1, uint32_t a2, uint32_t a3,
                                            uint32_t b0, uint32_t b1) {
    asm("mma.sync.aligned.m16n8k16.row.col.f32.f16.f16.f32 "
        "{%0,%1,%2,%3},{%4,%5,%6,%7},{%8,%9},{%0,%1,%2,%3};"
        : "+f"(d0), "+f"(d1), "+f"(d2), "+f"(d3)
        : "r"(a0), "r"(a1), "r"(a2), "r"(a3), "r"(b0), "r"(b1));
}

__global__ void pack_w_kernel(const float* __restrict__ W) {
    int i = blockIdx.x * blockDim.x + threadIdx.x;
    if (i < 152 * 32) {
        int kp = i >> 5, a = i & 31;
        float lo = (2 * kp     < C_COLS) ? W[(2 * kp)     * A_DIM + a] : 0.0f;
        float hi = (2 * kp + 1 < C_COLS) ? W[(2 * kp + 1) * A_DIM + a] : 0.0f;
        g_Wp[i] = pack_f16x2(lo, hi);
    }
}

__global__ __launch_bounds__(THREADS, 6)
void draftbot_kernel(const float* __restrict__ X,
                     const float* __restrict__ W,
                     float* __restrict__ Out)
{
    extern __shared__ uint32_t smw[];
    uint32_t* cardsp = smw;                          // [32][156] half2 (row x k-pairs)
    float*    apbuf  = (float*)(smw + CP_WORDS);     // [32][36]
    const int tid  = threadIdx.x;
    const int lane = tid & 31;
    const int warp = tid >> 5;
    float* pw   = apbuf + AP_WORDS + warp * PW_WORDS;
    int*   widx = (int*)pw;                          // [40]
    float* scw  = pw + IDXCAP;                       // [40]

    const int g = blockIdx.x;                        // this CTA's group

    // ---- stage cards of group g (f32 -> f16x2) ----
    {
        const float* gb = X + (size_t)g * GROUP * XSTRIDE + C_COLS;
        #pragma unroll 1
        for (int t = 0; t < 10; t++) {
            int idx = tid + THREADS * t;             // valid < 2400
            if (idx < GROUP * 75) {
                int row = idx / 75, ch = idx - row * 75;
                float4 v = *(const float4*)(gb + (size_t)row * XSTRIDE + 4 * ch);
                uint2 h;
                h.x = pack_f16x2(v.x, v.y);
                h.y = pack_f16x2(v.z, v.w);
                *(uint2*)(cardsp + row * CPS + 2 * ch) = h;
            }
        }
        if (tid < GROUP * 2) {                       // cardsp kp 150,151 = 0
            int r = tid >> 1, kp = 150 + (tid & 1);
            cardsp[r * CPS + kp] = 0u;
        }
    }
    __syncthreads();                                 // cards ready

    const unsigned FULL = 0xffffffffu;
    const int rt = warp & 1;                         // phase-1 row tile (16 rows)
    const int nt = warp >> 1;                        // phase-1 n tile (8 cols)
    const int gq = lane >> 2, tq = lane & 3;         // mma fragment coords
    const int qid = lane >> 3;                       // phase-2 octets
    const int sub = lane & 7;

    // ---------- phase 1: ap = cards @ W + 1  (fp16 m16n8k16, B from global L1) ----------
    {
        float d0 = 0.f, d1 = 0.f, d2 = 0.f, d3 = 0.f;
        const uint32_t* A0 = cardsp + (rt * 16 + gq) * CPS;
        const uint32_t* A1 = A0 + 8 * CPS;
        const uint32_t* Bp = g_Wp + nt * 8 + gq;     // L1-resident packed W
        #pragma unroll
        for (int kk = 0; kk < 19; kk++) {            // 19 * k16 = 304 (padded)
            const int kp0 = kk * 8;
            uint32_t a0 = A0[kp0 + tq];
            uint32_t a1 = A1[kp0 + tq];
            uint32_t a2 = A0[kp0 + tq + 4];
            uint32_t a3 = A1[kp0 + tq + 4];
            uint32_t b0 = __ldg(Bp + (kp0 + tq) * 32);
            uint32_t b1 = __ldg(Bp + (kp0 + tq + 4) * 32);
            mma_f16_k16(d0, d1, d2, d3, a0, a1, a2, a3, b0, b1);
        }
        float* ap0 = apbuf + (rt * 16 + gq) * APS + nt * 8 + 2 * tq;
        *(float2*)ap0             = make_float2(d0 + 1.f, d1 + 1.f);
        *(float2*)(ap0 + 8 * APS) = make_float2(d2 + 1.f, d3 + 1.f);
    }
    __syncthreads();                                 // ap ready

    // ---------- phase 2: 4 rows/warp, sparse scores + masked log-softmax ----------
    #pragma unroll 1
    for (int i = 0; i < 4; i++) {
        const int lrow = warp * 4 + i;
        const int grow = g * GROUP + lrow;

        // scan-based compaction (order-free) of nonzero option columns
        const float4* osrc = (const float4*)(X + (size_t)grow * XSTRIDE);
        float4 ovv[3];
        ovv[0] = osrc[lane];
        ovv[1] = (lane + 32 < 75) ? osrc[lane + 32] : make_float4(0,0,0,0);
        ovv[2] = (lane + 64 < 75) ? osrc[lane + 64] : make_float4(0,0,0,0);
        unsigned lm = 0;
        #pragma unroll
        for (int t = 0; t < 3; t++) {
            lm |= (ovv[t].x != 0.f ? 1u : 0u) << (4 * t + 0);
            lm |= (ovv[t].y != 0.f ? 1u : 0u) << (4 * t + 1);
            lm |= (ovv[t].z != 0.f ? 1u : 0u) << (4 * t + 2);
            lm |= (ovv[t].w != 0.f ? 1u : 0u) << (4 * t + 3);
        }
        int lc = __popc(lm);
        int incl = lc;
        #pragma unroll
        for (int o = 1; o < 32; o <<= 1) {
            int n = __shfl_up_sync(FULL, incl, o);
            if (lane >= o) incl += n;
        }
        int cn = __shfl_sync(FULL, incl, 31);
        int pos = incl - lc;
        unsigned mm = lm;
        while (mm) {
            int b = __ffs(mm) - 1; mm &= mm - 1;
            if (pos < IDXCAP) widx[pos] = 4 * (lane + 32 * (b >> 2)) + (b & 3);
            pos++;
        }
        if (cn > IDXCAP) cn = IDXCAP;
        __syncwarp();

        // scores: 8 lanes per column, 4 columns in flight (fp32 W from global, L1-hot)
        float4 av = *(const float4*)(apbuf + lrow * APS + sub * 4);
        const int nch = (cn + 3) >> 2;
        #pragma unroll 2
        for (int ch = 0; ch < nch; ch++) {
            int  j   = ch * 4 + qid;
            bool val = j < cn;
            int  c   = val ? widx[j] : 0;
            float4 wv = *(const float4*)(W + c * A_DIM + sub * 4);
            float p = av.x * wv.x + av.y * wv.y + av.z * wv.z + av.w * wv.w;
            p += __shfl_xor_sync(FULL, p, 1);
            p += __shfl_xor_sync(FULL, p, 2);
            p += __shfl_xor_sync(FULL, p, 4);
            if (val && sub == 0) scw[j] = p;
        }
        __syncwarp();

        // masked log-softmax (zeros always present in the row)
        int  j0 = lane, j1 = lane + 32;
        bool v0 = j0 < cn, v1 = j1 < cn;
        float s0 = v0 ? scw[j0] : 0.0f;
        float s1 = v1 ? scw[j1] : 0.0f;
        int   c0 = v0 ? widx[j0] : -1;
        int   c1 = v1 ? widx[j1] : -1;

        float m = fmaxf(fmaxf(s0, s1), 0.0f);
        #pragma unroll
        for (int o = 16; o > 0; o >>= 1) m = fmaxf(m, __shfl_xor_sync(FULL, m, o));

        float g0 = (s0 > 0.f) ? 1.f : ((s0 < 0.f) ? -1.f : 0.f);
        float g1 = (s1 > 0.f) ? 1.f : ((s1 < 0.f) ? -1.f : 0.f);
        float sum = g0 * __expf(s0 - m * g0) + g1 * __expf(s1 - m * g1);
        #pragma unroll
        for (int o = 16; o > 0; o >>= 1) sum += __shfl_xor_sync(FULL, sum, o);
        float lse = __logf(sum);

        float* orow = Out + (size_t)grow * C_COLS;
        #pragma unroll
        for (int t = 0; t < 3; t++) {
            int gi = lane + 32 * t;
            if (gi < 75) *(float4*)(orow + 4 * gi) = make_float4(0.f, 0.f, 0.f, 0.f);
        }
        __syncwarp();
        if (c0 >= 0) orow[c0] = g0 * ((s0 - m * g0) - lse);
        if (c1 >= 0) orow[c1] = g1 * ((s1 - m * g1) - lse);
        __syncwarp();
    }
}

extern "C" void kernel_launch(void* const* d_in, const int* in_sizes, int n_in,
                              void* d_out, int out_size)
{
    const float* X = (const float*)d_in[0];
    const float* W = (const float*)d_in[1];
    if (n_in >= 2 && in_sizes[0] < in_sizes[1]) {   // defensively order by size
        const float* t = X; X = W; W = t;
    }
    float* Out = (float*)d_out;

    cudaFuncSetAttribute(draftbot_kernel,
                         cudaFuncAttributeMaxDynamicSharedMemorySize, SMEM_BYTES);
    pack_w_kernel<<<19, 256>>>(W);
    draftbot_kernel<<<GRID, THREADS, SMEM_BYTES>>>(X, W, Out);
}